// round 13
// baseline (speedup 1.0000x reference)
#include <cuda_runtime.h>
#include <cuda_bf16.h>
#include <math.h>
#include <float.h>

// Fixed problem shapes
#define BB 32
#define NN 300
#define MM 50
#define NSLOT 10          // columns per lane: lanes 0..11 own 10, lanes 12..31 own 9

#define LAMBDA_POS 5.0
#define LAMBDA_CONF 2.0
#define LAMBDA_NOOBJ 0.5

#define FULLMASK 0xffffffffu

// Fixed-point scale 2^38 (resolution 3.6e-12); bias +2 keeps all costs > 0.
#define QSCALE 274877906944.0   // 2^38
#define CBIAS  2.0

#define GREEDY_PASSES 3

// Cross-block scratch (no cudaMalloc allowed)
__device__ double g_part[BB * 3];
__device__ int    g_done = 0;

__device__ __forceinline__ unsigned long long umin64(unsigned long long a, unsigned long long b) {
    return a < b ? a : b;
}
// warp argmin over packed u64 keys (key = (q<<9)|j, q >= 0): two u32 redux
__device__ __forceinline__ unsigned long long warp_min_key(unsigned long long mloc) {
    unsigned hi   = (unsigned)(mloc >> 32);
    unsigned hmin = __reduce_min_sync(FULLMASK, hi);
    unsigned lo   = (hi == hmin) ? (unsigned)mloc : 0xFFFFFFFFu;
    unsigned lmin = __reduce_min_sync(FULLMASK, lo);
    return ((unsigned long long)hmin << 32) | lmin;
}
__device__ __forceinline__ double softplus_d(double x) {
    return fmax(x, 0.0) + log1p(exp(-fabs(x)));
}

// Dynamic smem layout (8-byte entries first)
//   sq   [MM*NN] i64  packed cost keys (q<<9)|j
//   spq  [NN]    i64  shortest at removal (q units)
//   pkd  [NN]    i64  (u[row4col[j]]<<9) | (row4col[j]+1); 0 low bits = free
//   suq  [MM]    i64  dual u (q units)
//   sgt  [MM*2]  f32  staged gt
//   pb   [NN]    i32  pathback
//   r4c  [NN]    i32  row4col (-1 = free)  (cold uses only)
//   c4r  [MM]    i32  col4row (-1 = unassigned)
#define SMEM_QWORDS (MM * NN + NN + NN + MM)
#define SMEM_BYTES  (SMEM_QWORDS * 8 + MM * 2 * 4 + (NN + NN + MM) * 4)

__global__ void __launch_bounds__(32, 1)
detloss_kernel(const float* __restrict__ pred_c,  // [B,N,2]
               const float* __restrict__ conf,    // [B,N]
               const float* __restrict__ gt_c,    // [B,M,2]
               float* __restrict__ out)           // [5]
{
    const int b    = blockIdx.x;
    const int lane = threadIdx.x;

    const float* pc = pred_c + b * NN * 2;
    const float* cf = conf   + b * NN;
    const float* gc = gt_c   + b * MM * 2;

    extern __shared__ long long dyn[];
    long long* sq   = dyn;                  // [MM][NN]
    long long* spq  = sq + MM * NN;         // [NN]
    long long* pkd  = spq + NN;             // [NN]
    long long* suq  = pkd + NN;             // [MM]
    float*     sgt  = (float*)(suq + MM);   // [MM*2]
    int*       pb   = (int*)(sgt + MM * 2); // [NN]
    int*       r4c  = pb + NN;              // [NN]
    int*       c4r  = r4c + NN;             // [MM]

    // ---- Stage gt; init state ----
    for (int t = lane; t < MM * 2; t += 32) sgt[t] = gc[t];
    for (int j = lane; j < NN; j += 32) { r4c[j] = -1; pkd[j] = 0; }
    for (int m = lane; m < MM; m += 32) { suq[m] = 0; c4r[m] = -1; }
    __syncwarp();

    // ---- Build packed cost keys: q = rn((5*L1 - sigmoid + 2)*2^38) > 0 ----
    // Column j is built AND consumed by lane (j % 32): no sync needed on sq.
    #pragma unroll
    for (int k = 0; k < NSLOT; k++) {
        int j = k * 32 + lane;
        if (j < NN) {
            double x    = (double)cf[j];
            double base = (CBIAS - 1.0 / (1.0 + exp(-x))) * QSCALE;
            double px   = (double)pc[2 * j];
            double py   = (double)pc[2 * j + 1];
            for (int m = 0; m < MM; m++) {
                double dx = fabs(px - (double)sgt[2 * m]);
                double dy = fabs(py - (double)sgt[2 * m + 1]);
                long long q = __double2ll_rn(fma(dx + dy, 5.0 * QSCALE, base));
                sq[m * NN + j] = (q << 9) | (long long)j;
            }
        }
    }

    // per-lane register duals for owned columns (q units, <= 0)
    long long vq[NSLOT];
    #pragma unroll
    for (int k = 0; k < NSLOT; k++) vq[k] = 0;
    const unsigned validMask = (lane < 12) ? 0x3FFu : 0x1FFu;

    // ==== Phase 1: multi-pass greedy with exact reduction transfer ====
    // Per row: two smallest reduced costs mu1@j1, mu2.
    //  - j1 free:  assign; u[i]=mu2, v[j1] += (mu1-mu2)  (exact CS + feasible;
    //              matched columns become strictly unattractive)
    //  - j1 taken: u[i]=mu1 (tight feasible); retry next pass with updated v.
    for (int pass = 0; pass < GREEDY_PASSES; pass++) {
        int nun = 0;
        for (int i = 0; i < MM; i++) {
            if (pass > 0 && c4r[i] >= 0) continue;
            const long long* crow = sq + i * NN;
            unsigned long long k1 = ~0ULL, k2 = ~0ULL;
            #pragma unroll
            for (int k = 0; k < NSLOT; k++) {
                if (validMask & (1u << k)) {
                    unsigned long long ck =
                        (unsigned long long)(crow[k * 32 + lane] - (vq[k] << 9));
                    if (ck < k1) { k2 = k1; k1 = ck; }
                    else if (ck < k2) { k2 = ck; }
                }
            }
            // warp two-smallest via chained redux (keys unique: j in low bits)
            unsigned long long wk1 = warp_min_key(k1);
            unsigned long long cand = (k1 == wk1) ? k2 : k1;
            unsigned long long wk2 = warp_min_key(cand);

            int       j1  = (int)(wk1 & 511u);
            long long mu1 = (long long)(wk1 >> 9);
            long long mu2 = (long long)(wk2 >> 9);

            if ((pkd[j1] & 511) == 0) {          // column free (uniform branch)
                r4c[j1] = i;
                c4r[i]  = j1;
                suq[i]  = mu2;
                pkd[j1] = (mu2 << 9) | (long long)(i + 1);
                if ((j1 & 31) == lane) vq[j1 >> 5] += (mu1 - mu2);
            } else {
                suq[i] = mu1;
                nun++;
            }
        }
        if (nun == 0) break;
    }
    __syncwarp();

    // ==== Phase 2: shortest augmenting path (all-integer, exact) ====
    for (int cur = 0; cur < MM; cur++) {
        if (c4r[cur] >= 0) continue;

        unsigned long long skey[NSLOT];
        int pbk[NSLOT];
        #pragma unroll
        for (int k = 0; k < NSLOT; k++) { skey[k] = ~0ULL; pbk[k] = 0; }
        unsigned rem = validMask;
        unsigned remRound = 0;
        unsigned long long SR = 1ULL << cur;

        int       i    = cur;
        long long uiq  = suq[cur];
        long long minq = 0;
        int       sink;

        while (true) {
            long long pq = minq - uiq;
            const long long* crow = sq + i * NN;

            // relax: pure register updates
            #pragma unroll
            for (int k = 0; k < NSLOT; k++) {
                if (rem & (1u << k)) {
                    int j = k * 32 + lane;
                    long long off = (pq - vq[k]) << 9;
                    unsigned long long ck = (unsigned long long)(crow[j] + off);
                    if (ck < skey[k]) { skey[k] = ck; pbk[k] = i; }
                }
            }
            unsigned long long a0 = umin64(skey[0], skey[1]);
            unsigned long long a1 = umin64(skey[2], skey[3]);
            unsigned long long a2 = umin64(skey[4], skey[5]);
            unsigned long long a3 = umin64(skey[6], skey[7]);
            unsigned long long a4 = umin64(skey[8], skey[9]);
            unsigned long long mloc = umin64(umin64(umin64(a0, a1), umin64(a2, a3)), a4);

            unsigned long long mk = warp_min_key(mloc);
            int jst = (int)(mk & 511u);
            minq    = (long long)(mk >> 9);

            if (lane == 0) spq[jst] = minq;   // shortest value at removal
            if ((jst & 31) == lane) {         // owner retires its column
                int slot = jst >> 5;
                rem      &= ~(1u << slot);
                remRound |=  (1u << slot);
                #pragma unroll
                for (int k = 0; k < NSLOT; k++) {
                    if (k == slot) { skey[k] = ~0ULL; pb[jst] = pbk[k]; }
                }
            }

            long long w = pkd[jst];           // single LDS.64: (u<<9)|(row+1)
            int rr = (int)(w & 511);
            if (rr == 0) { sink = jst; break; }
            i   = rr - 1;
            uiq = (long long)(w >> 9);
            SR |= 1ULL << i;
        }

        __syncwarp();   // make spq/pb visible

        // dual updates (exact integer)
        for (int m = lane; m < MM; m += 32) {
            if (m == cur) {
                suq[m] += minq;
            } else if ((SR >> m) & 1) {
                suq[m] += minq - spq[c4r[m]];
            }
        }
        #pragma unroll
        for (int k = 0; k < NSLOT; k++) {
            if (remRound & (1u << k)) {
                int j = k * 32 + lane;
                vq[k] -= (minq - spq[j]);
            }
        }
        __syncwarp();

        // augment (lane 0)
        if (lane == 0) {
            int j = sink;
            while (true) {
                int ii = pb[j];
                r4c[j] = ii;
                int t = c4r[ii];
                c4r[ii] = j;
                j = t;
                if (ii == cur) break;
            }
        }
        __syncwarp();

        // refresh pkd for matched columns (u changed for SR rows + new sink)
        for (int m = lane; m < MM; m += 32) {
            int jm = c4r[m];
            if (jm >= 0) pkd[jm] = (suq[m] << 9) | (long long)(m + 1);
        }
        __syncwarp();
    }

    // ==== Loss partials (exact fp64 from original inputs) ====
    double pos = 0.0, obj = 0.0, noobj = 0.0;
    for (int m = lane; m < MM; m += 32) {
        int j = c4r[m];
        double dx = fabs((double)pc[2 * j]     - (double)sgt[2 * m]);
        double dy = fabs((double)pc[2 * j + 1] - (double)sgt[2 * m + 1]);
        pos += dx + dy;
        obj += softplus_d(-(double)cf[j]);
    }
    #pragma unroll
    for (int k = 0; k < NSLOT; k++) {
        int j = k * 32 + lane;
        if (j < NN && r4c[j] < 0)
            noobj += softplus_d((double)cf[j]);
    }
    #pragma unroll
    for (int off = 16; off; off >>= 1) {
        pos   += __shfl_xor_sync(FULLMASK, pos,   off);
        obj   += __shfl_xor_sync(FULLMASK, obj,   off);
        noobj += __shfl_xor_sync(FULLMASK, noobj, off);
    }
    int islast = 0;
    if (lane == 0) {
        g_part[b * 3 + 0] = pos   / (double)(MM * 2);
        g_part[b * 3 + 1] = obj   / (double)MM;
        g_part[b * 3 + 2] = noobj / (double)(NN - MM);
        __threadfence();
        int t = atomicAdd(&g_done, 1);
        islast = (t == BB - 1);
    }
    islast = __shfl_sync(FULLMASK, islast, 0);

    if (islast) {  // fused finalize
        __threadfence();
        double p = 0.0, o = 0.0, q = 0.0;
        if (lane < BB) {
            p = g_part[lane * 3 + 0];
            o = g_part[lane * 3 + 1];
            q = g_part[lane * 3 + 2];
        }
        #pragma unroll
        for (int off = 16; off; off >>= 1) {
            p += __shfl_xor_sync(FULLMASK, p, off);
            o += __shfl_xor_sync(FULLMASK, o, off);
            q += __shfl_xor_sync(FULLMASK, q, off);
        }
        if (lane == 0) {
            float lp = (float)(LAMBDA_POS   * p / (double)BB);
            float lo = (float)(LAMBDA_CONF  * o / (double)BB);
            float ln = (float)(LAMBDA_NOOBJ * q / (double)BB);
            out[0] = lp;
            out[1] = lo;
            out[2] = ln;
            out[3] = lp + lo + ln;
            out[4] = (float)MM;
            g_done = 0;   // self-reset for next graph replay
        }
    }
}

extern "C" void kernel_launch(void* const* d_in, const int* in_sizes, int n_in,
                              void* d_out, int out_size)
{
    const float* pred_c = (const float*)d_in[0];
    const float* conf   = (const float*)d_in[2];
    const float* gt_c   = (const float*)d_in[3];
    float* out = (float*)d_out;

    cudaFuncSetAttribute(detloss_kernel,
                         cudaFuncAttributeMaxDynamicSharedMemorySize, SMEM_BYTES);
    detloss_kernel<<<BB, 32, SMEM_BYTES>>>(pred_c, conf, gt_c, out);
}